// round 1
// baseline (speedup 1.0000x reference)
#include <cuda_runtime.h>
#include <cstddef>

// Problem constants (fixed by this problem instance)
#define Bb 2
#define Ss 512
#define Hh 8
#define Dd 64
#define Ee 512          // H*D
#define QT 32           // q rows per block
#define NRU 256         // relative index r in [0,256); actual use is [1,255]
#define EPITCH 65       // padded pitch for E slice in smem (odd -> conflict-free)
#define PUPITCH 257     // padded pitch for Pu in smem
#define NTHREADS 256

// Normalized x values (int32), filled by normalize_x_kernel each launch.
__device__ int g_xnorm[Bb * Ss];

// Detect whether x buffer is int64 or int32 (little-endian) and normalize to int32.
// For int64 input: 32-bit words are [x0_lo, 0, x1_lo, 0, ...] -> all odd words zero.
// For int32 input in [0,128): odd words are random x values; all-zero has ~0 probability.
// Only the first 1024 words (4 KB) are read for detection — valid for both dtypes.
__global__ void normalize_x_kernel(const int* __restrict__ xw) {
    __shared__ int is64;
    const int t = threadIdx.x;           // 512 threads
    if (t == 0) is64 = 1;
    __syncthreads();
    if (xw[2 * t + 1] != 0) atomicAnd(&is64, 0);
    __syncthreads();
    if (is64) {
        // safe: int64 buffer is 2048 words
        g_xnorm[2 * t]     = xw[4 * t];
        g_xnorm[2 * t + 1] = xw[4 * t + 2];
    } else {
        g_xnorm[2 * t]     = xw[2 * t];
        g_xnorm[2 * t + 1] = xw[2 * t + 1];
    }
}

// Fused kernel: per (b, h, q-tile) block
//  Phase 1 (GEMM): Pu[qi][r] = sum_d Q[qi][d] * E[r][d]  for r in [0,256)
//  Phase 2 (scatter): out[b,h,q0+qi,k] = Pu[qi][mx + x[b,k] - x[b,q0+qi]]
__global__ __launch_bounds__(NTHREADS)
void relpos_kernel(const float* __restrict__ qin,
                   const float* __restrict__ et,
                   const int*   __restrict__ mxp,
                   float*       __restrict__ out)
{
    extern __shared__ float sm[];
    float* sE  = sm;                       // [NRU][EPITCH]   256*65 floats
    float* sQ  = sE + NRU * EPITCH;        // [QT][Dd]        32*64
    float* sPu = sQ + QT * Dd;             // [QT][PUPITCH]   32*257
    int*   sX  = (int*)(sPu + QT * PUPITCH); // [Ss]          512 ints

    const int tid = threadIdx.x;
    const int q0  = blockIdx.x * QT;
    const int h   = blockIdx.y;
    const int b   = blockIdx.z;

    // Load per-head embed-table slice rows [0,256): E[r, h*64 + d]
    for (int i = tid; i < NRU * Dd; i += NTHREADS) {
        const int r = i >> 6, d = i & 63;
        sE[r * EPITCH + d] = et[r * Ee + h * Dd + d];
    }
    // Load Q tile: q[b, q0+qi, h, d]
    for (int i = tid; i < QT * Dd; i += NTHREADS) {
        const int qi = i >> 6, d = i & 63;
        sQ[i] = qin[(((size_t)b * Ss + q0 + qi) * Hh + h) * Dd + d];
    }
    // Load the whole x row for batch b (covers both x[k] and x[q0+qi])
    for (int k = tid; k < Ss; k += NTHREADS) sX[k] = g_xnorm[b * Ss + k];
    __syncthreads();

    // ---- Phase 1: register-blocked SMEM GEMM ----
    // Thread (tu = lane, tq = warp) computes qi in {4*tq..4*tq+3}, r in {tu + 32*j}.
    const int tu = tid & 31;
    const int tq = tid >> 5;

    float acc[4][8];
    #pragma unroll
    for (int i = 0; i < 4; ++i)
        #pragma unroll
        for (int j = 0; j < 8; ++j) acc[i][j] = 0.0f;

    #pragma unroll 4
    for (int d = 0; d < Dd; ++d) {
        float qv[4];
        #pragma unroll
        for (int i = 0; i < 4; ++i) qv[i] = sQ[(tq * 4 + i) * Dd + d]; // warp broadcast
        #pragma unroll
        for (int j = 0; j < 8; ++j) {
            const float e = sE[(tu + 32 * j) * EPITCH + d];            // conflict-free
            #pragma unroll
            for (int i = 0; i < 4; ++i) acc[i][j] = fmaf(qv[i], e, acc[i][j]);
        }
    }

    #pragma unroll
    for (int i = 0; i < 4; ++i)
        #pragma unroll
        for (int j = 0; j < 8; ++j)
            sPu[(tq * 4 + i) * PUPITCH + tu + 32 * j] = acc[i][j];
    __syncthreads();

    // ---- Phase 2: gather from Pu, coalesced stores ----
    const int mx  = mxp ? mxp[0] : 128;   // low 32-bit word valid for int32/int64 LE
    const int xk0 = sX[tid];
    const int xk1 = sX[tid + NTHREADS];
    float* ob = out + ((size_t)((b * Hh + h) * Ss + q0)) * Ss;

    #pragma unroll 4
    for (int qi = 0; qi < QT; ++qi) {
        const int base = qi * PUPITCH + mx - sX[q0 + qi];
        float* orow = ob + (size_t)qi * Ss;
        orow[tid]            = sPu[base + xk0];
        orow[tid + NTHREADS] = sPu[base + xk1];
    }
}

extern "C" void kernel_launch(void* const* d_in, const int* in_sizes, int n_in,
                              void* d_out, int out_size) {
    const float* q   = (const float*)d_in[0];
    const float* et  = (const float*)d_in[1];
    const int*   xw  = (const int*)d_in[2];
    const int*   mxp = (n_in > 3) ? (const int*)d_in[3] : nullptr;
    float*       out = (float*)d_out;

    (void)in_sizes; (void)out_size;

    normalize_x_kernel<<<1, 512>>>(xw);

    const size_t smem = (size_t)(NRU * EPITCH + QT * Dd + QT * PUPITCH) * sizeof(float)
                      + (size_t)Ss * sizeof(int);  // 109,696 bytes
    cudaFuncSetAttribute(relpos_kernel,
                         cudaFuncAttributeMaxDynamicSharedMemorySize, (int)smem);

    dim3 grid(Ss / QT, Hh, Bb);
    relpos_kernel<<<grid, NTHREADS, smem>>>(q, et, mxp, out);
}

// round 2
// speedup vs baseline: 1.1280x; 1.1280x over previous
#include <cuda_runtime.h>
#include <cstddef>

// Problem constants
#define Bb 2
#define Ss 512
#define Hh 8
#define Dd 64
#define Ee 512          // H*D
#define QT 32           // q rows per GEMM block
#define NRU 256         // relative index r in [0,256)
#define RP  258         // sEt pitch in floats ([d][r] transposed, 8B-aligned rows)
#define PPITCH 260      // scatter-kernel Pu pitch (16B-aligned rows for float4)

// Normalized x values (int32), filled by normalize_x_kernel each launch.
__device__ int g_xnorm[Bb * Ss];
// Pu scratch: [b][q][h][r] fp32 = 8 MB (fits in L2)
__device__ float g_pu[Bb * Ss * Hh * NRU];

// Detect int64 vs int32 x buffer (LE) and normalize to int32.
// int64 input -> all odd 32-bit words of the first 4 KB are zero.
__global__ void normalize_x_kernel(const int* __restrict__ xw) {
    __shared__ int is64;
    const int t = threadIdx.x;           // 512 threads
    if (t == 0) is64 = 1;
    __syncthreads();
    if (xw[2 * t + 1] != 0) atomicAnd(&is64, 0);
    __syncthreads();
    if (is64) {
        g_xnorm[2 * t]     = xw[4 * t];
        g_xnorm[2 * t + 1] = xw[4 * t + 2];
    } else {
        g_xnorm[2 * t]     = xw[2 * t];
        g_xnorm[2 * t + 1] = xw[2 * t + 1];
    }
}

// ---------------- Kernel A: Pu[b,q,h,r] = sum_d Q[b,q,h,d] * E[r, h*64+d] ----------------
// Block = (qtile, h, b). 256 threads. Per thread: 4 q x 8 r as 16 f32x2 accumulators.
__global__ __launch_bounds__(256, 3)
void pu_gemm_kernel(const float* __restrict__ qin,
                    const float* __restrict__ et)
{
    extern __shared__ float sm[];
    float* sEt = sm;                 // [Dd][RP]  E transposed: sEt[d*RP + r]
    float* sQ  = sm + Dd * RP;       // [QT][Dd]

    const int tid = threadIdx.x;
    const int q0  = blockIdx.x * QT;
    const int h   = blockIdx.y;
    const int b   = blockIdx.z;

    // Load E slice transposed: global read coalesced over d, smem store 2-way conflict (once).
    for (int i = tid; i < NRU * Dd; i += 256) {
        const int r = i >> 6, d = i & 63;
        sEt[d * RP + r] = et[r * Ee + h * Dd + d];
    }
    // Load Q tile (coalesced over d)
    for (int i = tid; i < QT * Dd; i += 256) {
        const int qi = i >> 6, d = i & 63;
        sQ[i] = qin[(((size_t)b * Ss + q0 + qi) * Hh + h) * Dd + d];
    }
    __syncthreads();

    const int l = tid & 31;          // lane -> r-pairs {l, l+32, l+64, l+96}
    const int w = tid >> 5;          // warp -> q in {4w .. 4w+3}

    unsigned long long acc[4][4];
    #pragma unroll
    for (int i = 0; i < 4; ++i)
        #pragma unroll
        for (int j = 0; j < 4; ++j) acc[i][j] = 0ULL;

    #pragma unroll 8
    for (int d = 0; d < Dd; ++d) {
        unsigned long long e2[4], q2[4];
        #pragma unroll
        for (int j = 0; j < 4; ++j)   // LDS.64 of (e_r, e_{r+1}), conflict-free
            e2[j] = *(const unsigned long long*)&sEt[d * RP + 2 * (l + 32 * j)];
        #pragma unroll
        for (int i = 0; i < 4; ++i) { // warp-broadcast q, duplicate into both halves
            const unsigned int qb = __float_as_uint(sQ[(4 * w + i) * Dd + d]);
            asm("mov.b64 %0, {%1, %1};" : "=l"(q2[i]) : "r"(qb));
        }
        #pragma unroll
        for (int i = 0; i < 4; ++i)
            #pragma unroll
            for (int j = 0; j < 4; ++j)
                asm("fma.rn.f32x2 %0, %1, %2, %3;"
                    : "=l"(acc[i][j]) : "l"(q2[i]), "l"(e2[j]), "l"(acc[i][j]));
    }

    // Write Pu[b][q][h][r]: per (i,j) lanes write consecutive 8B -> coalesced.
    #pragma unroll
    for (int i = 0; i < 4; ++i) {
        const size_t base = (((size_t)b * Ss + q0 + 4 * w + i) * Hh + h) * NRU;
        #pragma unroll
        for (int j = 0; j < 4; ++j)
            *(unsigned long long*)&g_pu[base + 2 * (l + 32 * j)] = acc[i][j];
    }
}

// ---------------- Kernel B: out[b,h,q,k] = Pu[b,q,h, mx + x[b,k] - x[b,q]] ----------------
// Block = (q, b). 256 threads, each handles k = tid and k = tid+256 for all 8 heads.
__global__ __launch_bounds__(256)
void scatter_kernel(float* __restrict__ out, const int* __restrict__ mxp)
{
    __shared__ float sP[Hh * PPITCH];

    const int tid = threadIdx.x;
    const int q   = blockIdx.x;
    const int b   = blockIdx.y;

    // Load Pu rows for all heads: 8 KB contiguous, float4.
    const float4* src = (const float4*)&g_pu[(((size_t)b * Ss + q) * Hh) * NRU];
    for (int i = tid; i < Hh * (NRU / 4); i += 256) {
        const int h = i >> 6, r4 = i & 63;
        *(float4*)&sP[h * PPITCH + r4 * 4] = src[i];
    }

    const int mx  = mxp ? mxp[0] : 128;  // LE low word valid for int32/int64
    const int xq  = g_xnorm[b * Ss + q];
    const int i0  = mx + g_xnorm[b * Ss + tid] - xq;
    const int i1  = mx + g_xnorm[b * Ss + tid + 256] - xq;
    __syncthreads();

    #pragma unroll
    for (int h = 0; h < Hh; ++h) {
        float* orow = out + (((size_t)(b * Hh + h) * Ss + q)) * Ss;
        orow[tid]       = sP[h * PPITCH + i0];
        orow[tid + 256] = sP[h * PPITCH + i1];
    }
}

extern "C" void kernel_launch(void* const* d_in, const int* in_sizes, int n_in,
                              void* d_out, int out_size) {
    const float* q   = (const float*)d_in[0];
    const float* et  = (const float*)d_in[1];
    const int*   xw  = (const int*)d_in[2];
    const int*   mxp = (n_in > 3) ? (const int*)d_in[3] : nullptr;
    float*       out = (float*)d_out;
    (void)in_sizes; (void)out_size;

    normalize_x_kernel<<<1, 512>>>(xw);

    const int smemA = (Dd * RP + QT * Dd) * sizeof(float);  // 74,240 B
    cudaFuncSetAttribute(pu_gemm_kernel,
                         cudaFuncAttributeMaxDynamicSharedMemorySize, smemA);

    dim3 gridA(Ss / QT, Hh, Bb);     // 16 x 8 x 2 = 256 blocks
    pu_gemm_kernel<<<gridA, 256, smemA>>>(q, et);

    dim3 gridB(Ss, Bb);              // 512 x 2 = 1024 blocks
    scatter_kernel<<<gridB, 256>>>(out, mxp);
}